// round 1
// baseline (speedup 1.0000x reference)
#include <cuda_runtime.h>
#include <math.h>
#include <stdint.h>

#define NTEST  8192
#define NTRAIN 8192
#define NFEAT  64

// ---- device scratch (no allocations allowed) ----
__device__ float        g_w[NFEAT];
__device__ float        g_base;
__device__ unsigned char g_tcode[NTEST * NFEAT];
__device__ unsigned char g_scode[NTRAIN * NFEAT];
__device__ unsigned int g_rowmax[NTEST];   // order-preserving uint encoding of float max

// Order-preserving float -> uint map (monotone): larger float => larger uint.
__device__ __forceinline__ unsigned int f2key(float f) {
    unsigned int u = __float_as_uint(f);
    return (u & 0x80000000u) ? ~u : (u | 0x80000000u);
}
__device__ __forceinline__ float key2f(unsigned int k) {
    return (k & 0x80000000u) ? __uint_as_float(k ^ 0x80000000u) : __uint_as_float(~k);
}

// ---------------------------------------------------------------------------
// Kernel 1: per-feature weights + base scalar
// ---------------------------------------------------------------------------
__global__ void prep_w_kernel(const float* __restrict__ bw) {
    __shared__ float red[64];
    int t = threadIdx.x;              // 64 threads
    float h  = bw[t];
    float lf = logf(h * (1.0f / 3.0f));   // log(h/(L-1)), L=4
    float lt = logf(1.0f - h);
    g_w[t]   = lt - lf;
    red[t]   = lf - logf(h);
    __syncthreads();
    for (int s = 32; s > 0; s >>= 1) {
        if (t < s) red[t] += red[t + s];
        __syncthreads();
    }
    if (t == 0) g_base = red[0];
}

// ---------------------------------------------------------------------------
// Kernel 2: float -> uint8 codes, and rowmax init
// ---------------------------------------------------------------------------
__global__ void prep_codes_kernel(const float* __restrict__ test,
                                  const float* __restrict__ train) {
    int i = blockIdx.x * blockDim.x + threadIdx.x;
    const int n = NTEST * NFEAT;
    if (i < n) {
        g_tcode[i] = (unsigned char)test[i];
        g_scode[i] = (unsigned char)train[i];
    }
    if (i < NTEST) g_rowmax[i] = 0u;  // key 0 == smaller than any real value's key
}

// ---------------------------------------------------------------------------
// Kernel 3: comparison-GEMM.  Each CTA: 128x128 tile. 256 threads, 8x8/thread.
// log_dist = base + sum_f w_f * [tcode==scode]; writes log_dist to out and
// fuses per-row running max via atomicMax on encoded keys.
// ---------------------------------------------------------------------------
__global__ __launch_bounds__(256, 2) void gemm_kernel(float* __restrict__ out) {
    __shared__ unsigned char a_s[NFEAT][128];   // feature-major: a_s[f][m]
    __shared__ unsigned char b_s[NFEAT][128];
    __shared__ float w_s[NFEAT];

    const int t  = threadIdx.x;
    const int tx = t & 15;        // 0..15 -> 8 cols each
    const int ty = t >> 4;        // 0..15 -> 8 rows each
    const int row0 = blockIdx.y * 128;
    const int col0 = blockIdx.x * 128;

    if (t < NFEAT) w_s[t] = g_w[t];

    // Tiles are contiguous 8KB blocks in global (64B/row * 128 rows).
    const uint32_t* ta = (const uint32_t*)(g_tcode + (size_t)row0 * NFEAT);
    const uint32_t* tb = (const uint32_t*)(g_scode + (size_t)col0 * NFEAT);
    #pragma unroll
    for (int it = 0; it < 8; it++) {
        int idx = t + it * 256;               // 0..2047 u32 words
        uint32_t va = ta[idx];
        uint32_t vb = tb[idx];
        int r  = idx >> 4;                    // row within tile
        int f0 = (idx & 15) << 2;             // first feature in this word
        #pragma unroll
        for (int k = 0; k < 4; k++) {
            a_s[f0 + k][r] = (unsigned char)((va >> (8 * k)) & 0xFF);
            b_s[f0 + k][r] = (unsigned char)((vb >> (8 * k)) & 0xFF);
        }
    }
    __syncthreads();

    float acc[8][8];
    #pragma unroll
    for (int m = 0; m < 8; m++)
        #pragma unroll
        for (int n = 0; n < 8; n++) acc[m][n] = 0.0f;

    #pragma unroll 4
    for (int f = 0; f < NFEAT; f++) {
        uint2 av = *(const uint2*)&a_s[f][ty * 8];
        uint2 bv = *(const uint2*)&b_s[f][tx * 8];
        float wf = w_s[f];
        unsigned int am[8], bn[8];
        #pragma unroll
        for (int k = 0; k < 4; k++) {
            am[k]     = (av.x >> (8 * k)) & 0xFF;
            am[k + 4] = (av.y >> (8 * k)) & 0xFF;
            bn[k]     = (bv.x >> (8 * k)) & 0xFF;
            bn[k + 4] = (bv.y >> (8 * k)) & 0xFF;
        }
        #pragma unroll
        for (int m = 0; m < 8; m++)
            #pragma unroll
            for (int n = 0; n < 8; n++)
                if (am[m] == bn[n]) acc[m][n] += wf;   // ISETP + @P FADD
    }

    const float base = g_base;

    #pragma unroll
    for (int m = 0; m < 8; m++) {
        int row = row0 + ty * 8 + m;
        float vals[8];
        float rmax = -INFINITY;
        #pragma unroll
        for (int n = 0; n < 8; n++) {
            vals[n] = acc[m][n] + base;
            rmax = fmaxf(rmax, vals[n]);
        }
        float4* p = (float4*)(out + (size_t)row * NTRAIN + col0 + tx * 8);
        p[0] = make_float4(vals[0], vals[1], vals[2], vals[3]);
        p[1] = make_float4(vals[4], vals[5], vals[6], vals[7]);

        // reduce rmax across the 16 lanes that share this row (tx = 0..15,
        // which are lanes [0..15] or [16..31] of the warp).
        #pragma unroll
        for (int o = 8; o >= 1; o >>= 1)
            rmax = fmaxf(rmax, __shfl_xor_sync(0xFFFFFFFFu, rmax, o));
        if (tx == 0) atomicMax(&g_rowmax[row], f2key(rmax));
    }
}

// ---------------------------------------------------------------------------
// Kernel 4: out[i,j] = max_i * exp(out[i,j] - max_i)   (in-place)
// ---------------------------------------------------------------------------
__global__ void finalize_kernel(float* __restrict__ out) {
    int row = blockIdx.y;
    int col = (blockIdx.x * blockDim.x + threadIdx.x) * 4;
    float mx = key2f(g_rowmax[row]);
    float4* p = (float4*)(out + (size_t)row * NTRAIN + col);
    float4 v = *p;
    v.x = mx * __expf(v.x - mx);
    v.y = mx * __expf(v.y - mx);
    v.z = mx * __expf(v.z - mx);
    v.w = mx * __expf(v.w - mx);
    *p = v;
}

// ---------------------------------------------------------------------------
extern "C" void kernel_launch(void* const* d_in, const int* in_sizes, int n_in,
                              void* d_out, int out_size) {
    const float* bw    = (const float*)d_in[0];
    const float* test  = (const float*)d_in[1];
    const float* train = (const float*)d_in[2];
    float* out = (float*)d_out;
    (void)in_sizes; (void)n_in; (void)out_size;

    prep_w_kernel<<<1, 64>>>(bw);
    prep_codes_kernel<<<(NTEST * NFEAT + 255) / 256, 256>>>(test, train);

    dim3 grid(NTRAIN / 128, NTEST / 128);
    gemm_kernel<<<grid, 256>>>(out);

    finalize_kernel<<<dim3(NTRAIN / (256 * 4), NTEST), 256>>>(out);
}

// round 8
// speedup vs baseline: 1.6645x; 1.6645x over previous
#include <cuda_runtime.h>
#include <cuda_bf16.h>
#include <math.h>
#include <stdint.h>

#define NTEST  8192
#define NTRAIN 8192
#define NFEAT  64
#define KTOT   256        // 64 feats * 4 levels (one-hot indicators)
#define TILE_M 128
#define TILE_N 256
#define KC     32         // k elems per pipeline chunk
#define NCHUNK (KTOT / KC)       // 8
#define STAGES 4
#define A_STG  (TILE_M * KC * 2)     // 8192 B  (one plane)
#define B_STG  (TILE_N * KC * 2)     // 16384 B
#define STG    (2 * A_STG + B_STG)   // 32768 B  [Ahi | Alo | B]
#define DYN_SMEM (STAGES * STG + 1024)

// ---- device scratch (no allocations) ----
__device__ __align__(256) unsigned short g_Ahi[NTEST * KTOT];   // 4 MB
__device__ __align__(256) unsigned short g_Alo[NTEST * KTOT];   // 4 MB
__device__ __align__(256) unsigned short g_B  [NTRAIN * KTOT];  // 4 MB
__device__ unsigned short g_whb[NFEAT], g_wlb[NFEAT];
__device__ float          g_base;
__device__ unsigned int   g_rowmax[NTEST];

// ---------------- helpers ----------------
__device__ __forceinline__ unsigned int f2key(float f) {
    unsigned int u = __float_as_uint(f);
    return (u & 0x80000000u) ? ~u : (u | 0x80000000u);
}
__device__ __forceinline__ float key2f(unsigned int k) {
    return (k & 0x80000000u) ? __uint_as_float(k ^ 0x80000000u) : __uint_as_float(~k);
}
__device__ __forceinline__ uint32_t smem_u32(const void* p) {
    uint32_t a;
    asm("{ .reg .u64 t; cvta.to.shared.u64 t, %1; cvt.u32.u64 %0, t; }" : "=r"(a) : "l"(p));
    return a;
}
// 64B rows; XOR-swizzle 16B chunks so any 8 consecutive rows hit 8 distinct
// 16B bank columns (conflict-free ldmatrix + cp.async stores).
__device__ __forceinline__ uint32_t swz(int r, int c16) {
    return (uint32_t)(r * 64 + ((c16 ^ ((r >> 1) & 3)) << 4));
}
#define CP16(dst, src) \
    asm volatile("cp.async.cg.shared.global [%0], [%1], 16;" :: "r"(dst), "l"(src))
#define CP_COMMIT()  asm volatile("cp.async.commit_group;" ::: "memory")
#define CP_WAIT2()   asm volatile("cp.async.wait_group 2;" ::: "memory")
#define LDSM_X4(r0,r1,r2,r3,addr) \
    asm volatile("ldmatrix.sync.aligned.m8n8.x4.shared.b16 {%0,%1,%2,%3}, [%4];" \
        : "=r"(r0),"=r"(r1),"=r"(r2),"=r"(r3) : "r"(addr))
__device__ __forceinline__ void mma16816(float* d, const uint32_t* a, const uint32_t* b) {
    asm volatile(
        "mma.sync.aligned.m16n8k16.row.col.f32.bf16.bf16.f32 "
        "{%0,%1,%2,%3}, {%4,%5,%6,%7}, {%8,%9}, {%0,%1,%2,%3};"
        : "+f"(d[0]), "+f"(d[1]), "+f"(d[2]), "+f"(d[3])
        : "r"(a[0]), "r"(a[1]), "r"(a[2]), "r"(a[3]), "r"(b[0]), "r"(b[1]));
}

// ---------------------------------------------------------------------------
// Kernel 1: weights (bf16 hi/lo split) + base scalar
// ---------------------------------------------------------------------------
__global__ void prep_w_kernel(const float* __restrict__ bw) {
    __shared__ float red[64];
    int t = threadIdx.x;                    // 64 threads
    float h  = bw[t];
    float lf = logf(h * (1.0f / 3.0f));     // log(h/(L-1)), L=4
    float lt = logf(1.0f - h);
    float w  = lt - lf;
    __nv_bfloat16 wh = __float2bfloat16(w);
    float whf = __bfloat162float(wh);
    __nv_bfloat16 wl = __float2bfloat16(w - whf);
    g_whb[t] = *(unsigned short*)&wh;
    g_wlb[t] = *(unsigned short*)&wl;
    red[t] = lf - logf(h);
    __syncthreads();
    for (int s = 32; s > 0; s >>= 1) { if (t < s) red[t] += red[t + s]; __syncthreads(); }
    if (t == 0) g_base = red[0];
}

// ---------------------------------------------------------------------------
// Kernel 2: build one-hot bf16 operand planes; k col = f*4 + lvl
// ---------------------------------------------------------------------------
__global__ void prep_build_kernel(const float* __restrict__ test,
                                  const float* __restrict__ train) {
    int tid = blockIdx.x * blockDim.x + threadIdx.x;   // 0 .. 2*8192*64-1
    if (tid < NTEST) g_rowmax[tid] = 0u;
    int half = tid >> 19;                  // 8192*64 = 2^19
    int r    = (tid >> 6) & 8191;
    int f    = tid & 63;
    if (half == 0) {
        int code = (int)test[r * NFEAT + f];
        uint32_t sh = (uint32_t)(code & 1) * 16;
        uint32_t h0 = 0, h1 = 0, l0 = 0, l1 = 0;
        uint32_t wh = g_whb[f], wl = g_wlb[f];
        if (code < 2) { h0 = wh << sh; l0 = wl << sh; }
        else          { h1 = wh << sh; l1 = wl << sh; }
        ((uint2*)g_Ahi)[r * (KTOT / 4) + f] = make_uint2(h0, h1);
        ((uint2*)g_Alo)[r * (KTOT / 4) + f] = make_uint2(l0, l1);
    } else {
        int code = (int)train[r * NFEAT + f];
        uint32_t sh = (uint32_t)(code & 1) * 16;
        uint32_t b0 = 0, b1 = 0;
        if (code < 2) b0 = 0x3F80u << sh; else b1 = 0x3F80u << sh;   // bf16 1.0
        ((uint2*)g_B)[r * (KTOT / 4) + f] = make_uint2(b0, b1);
    }
}

// ---------------------------------------------------------------------------
// Kernel 3: mma.sync bf16 GEMM.  CTA 128x256, 512 thr (4x4 warps, warp 32x64).
// 4-stage cp.async pipeline; epilogue fuses +base, row-max, store.
// ---------------------------------------------------------------------------
__global__ __launch_bounds__(512, 1) void gemm_kernel(float* __restrict__ out) {
    extern __shared__ unsigned char dsm[];
    const uint32_t smem0 = (smem_u32(dsm) + 1023u) & ~1023u;

    const int t = threadIdx.x, lane = t & 31, wid = t >> 5;
    const int wm = wid & 3;            // m-block of 32 rows
    const int wn = wid >> 2;           // n-block of 64 cols
    const int row0 = blockIdx.y * TILE_M;
    const int col0 = blockIdx.x * TILE_N;

    // per-lane ldmatrix source coords (A and B both non-trans: n-major B is
    // already col-major for mma row.col, QK^T-style)
    const int a_r = (lane & 7) + ((lane >> 3) & 1) * 8;   // row within m16 tile
    const int a_c = (lane >> 4) & 1;                      // k16-half (16B sel)
    const int b_r = (lane & 7) + ((lane >> 4) & 1) * 8;   // n row within n16 pair
    const int b_c = (lane >> 3) & 1;                      // k8-half (16B sel)

    float d[2][8][4];
    #pragma unroll
    for (int mt = 0; mt < 2; mt++)
        #pragma unroll
        for (int nt = 0; nt < 8; nt++)
            #pragma unroll
            for (int q = 0; q < 4; q++) d[mt][nt][q] = 0.0f;

    // ---- stage loader: 2048 x 16B per stage, 4 per thread ----
    auto load_stage = [&](int s, int c) {
        uint32_t sb = smem0 + s * STG;
        {   // A-hi: 128 rows x 4 chunks
            int r = t >> 2, c16 = t & 3;
            CP16(sb + swz(r, c16),
                 g_Ahi + (size_t)(row0 + r) * KTOT + c * KC + c16 * 8);
        }
        {   // A-lo
            int r = t >> 2, c16 = t & 3;
            CP16(sb + A_STG + swz(r, c16),
                 g_Alo + (size_t)(row0 + r) * KTOT + c * KC + c16 * 8);
        }
        #pragma unroll
        for (int it = 0; it < 2; it++) {   // B: 256 rows x 4 chunks
            int j = it * 512 + t;
            int r = j >> 2, c16 = j & 3;
            CP16(sb + 2 * A_STG + swz(r, c16),
                 g_B + (size_t)(col0 + r) * KTOT + c * KC + c16 * 8);
        }
    };

    // prologue: fill 3 stages
    #pragma unroll
    for (int c = 0; c < STAGES - 1; c++) { load_stage(c, c); CP_COMMIT(); }

    #pragma unroll 1
    for (int c = 0; c < NCHUNK; c++) {
        CP_WAIT2();            // chunk c resident
        __syncthreads();       // everyone done reading the stage being refilled
        if (c + STAGES - 1 < NCHUNK) load_stage((c + STAGES - 1) & 3, c + STAGES - 1);
        CP_COMMIT();

        uint32_t sa_hi = smem0 + (c & 3) * STG;
        uint32_t sa_lo = sa_hi + A_STG;
        uint32_t sb    = sa_lo + A_STG;

        #pragma unroll
        for (int kk = 0; kk < 2; kk++) {           // two k16 steps per chunk
            uint32_t ah[2][4], al[2][4], bb[8][2];
            #pragma unroll
            for (int mt = 0; mt < 2; mt++) {
                int r = wm * 32 + mt * 16 + a_r;
                LDSM_X4(ah[mt][0], ah[mt][1], ah[mt][2], ah[mt][3],
                        sa_hi + swz(r, kk * 2 + a_c));
                LDSM_X4(al[mt][0], al[mt][1], al[mt][2], al[mt][3],
                        sa_lo + swz(r, kk * 2 + a_c));
            }
            #pragma unroll
            for (int p = 0; p < 4; p++) {          // 2 n8-tiles per x4 (non-trans)
                int r = wn * 64 + p * 16 + b_r;
                uint32_t r0, r1, r2, r3;
                LDSM_X4(r0, r1, r2, r3, sb + swz(r, kk * 2 + b_c));
                bb[p * 2][0]     = r0;  bb[p * 2][1]     = r1;
                bb[p * 2 + 1][0] = r2;  bb[p * 2 + 1][1] = r3;
            }
            #pragma unroll
            for (int mt = 0; mt < 2; mt++)
                #pragma unroll
                for (int nt = 0; nt < 8; nt++) {
                    mma16816(d[mt][nt], ah[mt], bb[nt]);
                    mma16816(d[mt][nt], al[mt], bb[nt]);
                }
        }
    }

    // ---- epilogue: +base, store, fused row-max ----
    const float base = g_base;
    const int group = lane >> 2, tig = lane & 3;
    #pragma unroll
    for (int mt = 0; mt < 2; mt++) {
        #pragma unroll
        for (int hf = 0; hf < 2; hf++) {
            int row = row0 + wm * 32 + mt * 16 + hf * 8 + group;
            float* orow = out + (size_t)row * NTRAIN + col0 + wn * 64;
            float rm = -INFINITY;
            #pragma unroll
            for (int nt = 0; nt < 8; nt++) {
                float v0 = d[mt][nt][hf * 2 + 0] + base;
                float v1 = d[mt][nt][hf * 2 + 1] + base;
                rm = fmaxf(rm, fmaxf(v0, v1));
                *(float2*)(orow + nt * 8 + tig * 2) = make_float2(v0, v1);
            }
            rm = fmaxf(rm, __shfl_xor_sync(0xFFFFFFFFu, rm, 1));
            rm = fmaxf(rm, __shfl_xor_sync(0xFFFFFFFFu, rm, 2));
            if (tig == 0) atomicMax(&g_rowmax[row], f2key(rm));
        }
    }
}

// ---------------------------------------------------------------------------
// Kernel 4: out[i,j] = max_i * exp(out[i,j] - max_i)   (in-place)
// ---------------------------------------------------------------------------
__global__ void finalize_kernel(float* __restrict__ out) {
    int row = blockIdx.y;
    int col = (blockIdx.x * blockDim.x + threadIdx.x) * 4;
    float mx = key2f(g_rowmax[row]);
    float4* p = (float4*)(out + (size_t)row * NTRAIN + col);
    float4 v = *p;
    v.x = mx * __expf(v.x - mx);
    v.y = mx * __expf(v.y - mx);
    v.z = mx * __expf(v.z - mx);
    v.w = mx * __expf(v.w - mx);
    *p = v;
}

// ---------------------------------------------------------------------------
extern "C" void kernel_launch(void* const* d_in, const int* in_sizes, int n_in,
                              void* d_out, int out_size) {
    const float* bw    = (const float*)d_in[0];
    const float* test  = (const float*)d_in[1];
    const float* train = (const float*)d_in[2];
    float* out = (float*)d_out;
    (void)in_sizes; (void)n_in; (void)out_size;

    cudaFuncSetAttribute(gemm_kernel, cudaFuncAttributeMaxDynamicSharedMemorySize, DYN_SMEM);

    prep_w_kernel<<<1, 64>>>(bw);
    prep_build_kernel<<<(2 * NTEST * NFEAT) / 256, 256>>>(test, train);

    dim3 grid(NTRAIN / TILE_N, NTEST / TILE_M);   // (32, 64)
    gemm_kernel<<<grid, 512, DYN_SMEM>>>(out);

    finalize_kernel<<<dim3(NTRAIN / (256 * 4), NTEST), 256>>>(out);
}